// round 6
// baseline (speedup 1.0000x reference)
#include <cuda_runtime.h>

#define BB 2
#define NCH 7
#define VV 2097152          // 32*256*256
#define NI 16
#define NSG 17
#define NBINS 4096
#define SLOTS 4

// accumulator layout (floats)
#define OFF_CNT   0          // BB*NSG
#define OFF_SSUM  34         // BB*NSG*3
#define OFF_SSQ   136
#define OFF_XYZ   238
#define OFF_CCNT  340
#define OFF_CXYZ  374
#define OFF_VAR   476        // BB
#define OFF_SBG   478
#define OFF_SFG   480
#define OFF_ILOSS 482
#define OFF_S     484        // BB*NI*3
#define OFF_CEN   580        // BB*NI*3
#define ACC_N     676

__device__ float g_acc[ACC_N];                          // zero-init; self-cleaning
__device__ unsigned g_hfg[BB * NI * NBINS * SLOTS];     // 2MB  fg counts
__device__ unsigned g_hbg[BB * NI * NBINS * SLOTS];     // 2MB  bg counts

__device__ __forceinline__ float fast_tanh(float x) {
    float r;
    asm("tanh.approx.f32 %0, %1;" : "=f"(r) : "f"(x));
    return r;
}

// ---------------------------------------------------------------- stats
// Per-warp fixed-point packed accumulators (3 u64 per id), exact/bounded for
// exactly 256 voxels per warp. grid (1024, BB), 256 thr, 8 voxels/thread.
// pack A: [xs:0..17)(max 65280) [ys:17..34) [zs:34..48)(max 7936) [cnt:48..58)
// pack B: q = rn((clamp(s,±15.5)+16)*256) <= 8064 ; fields 21 bits, sum<2^21
// pack C: r = rn(s*s*32) <= 7688 ; fields 21 bits
__global__ void __launch_bounds__(256) k_stats(const float* __restrict__ pred,
                                               const int* __restrict__ inst,
                                               const int* __restrict__ cent) {
    int b = blockIdx.y;
    __shared__ unsigned long long wacc[8][NSG][3];
    __shared__ float sm[NSG * 10];
    int tid = threadIdx.x;
    int warp = tid >> 5, lane = tid & 31;

    for (int j = tid; j < 8 * NSG * 3; j += 256)
        ((unsigned long long*)wacc)[j] = 0ull;
    for (int j = tid; j < NSG * 10; j += 256) sm[j] = 0.0f;
    __syncthreads();

    const float* sig = pred + ((size_t)b * NCH + 3) * VV;
    const int* ib = inst + (size_t)b * VV;
    const int* cb = cent + (size_t)b * VV;

    int v0 = (blockIdx.x * 256 + tid) * 8;
#pragma unroll
    for (int g = 0; g < 2; g++) {
        int vb = v0 + g * 4;
        float4 f0 = *(const float4*)(sig + vb);
        float4 f1 = *(const float4*)(sig + VV + vb);
        float4 f2 = *(const float4*)(sig + 2 * VV + vb);
        int4 iv = *(const int4*)(ib + vb);
        int4 cv = *(const int4*)(cb + vb);
        float a0[4] = {f0.x, f0.y, f0.z, f0.w};
        float a1[4] = {f1.x, f1.y, f1.z, f1.w};
        float a2[4] = {f2.x, f2.y, f2.z, f2.w};
        int ia[4] = {iv.x, iv.y, iv.z, iv.w};
        int ca[4] = {cv.x, cv.y, cv.z, cv.w};
#pragma unroll
        for (int k = 0; k < 4; k++) {
            int v = vb + k;
            int id = ia[k];
            float s0 = fminf(fmaxf(a0[k], -15.5f), 15.5f);
            float s1 = fminf(fmaxf(a1[k], -15.5f), 15.5f);
            float s2 = fminf(fmaxf(a2[k], -15.5f), 15.5f);
            unsigned xi = v & 255;
            unsigned yi = (v >> 8) & 255;
            unsigned zi = (unsigned)v >> 16;
            unsigned long long* base = wacc[warp][id];
            unsigned q0 = __float2uint_rn((s0 + 16.0f) * 256.0f);
            unsigned q1 = __float2uint_rn((s1 + 16.0f) * 256.0f);
            unsigned q2 = __float2uint_rn((s2 + 16.0f) * 256.0f);
            unsigned r0 = __float2uint_rn(s0 * s0 * 32.0f);
            unsigned r1 = __float2uint_rn(s1 * s1 * 32.0f);
            unsigned r2 = __float2uint_rn(s2 * s2 * 32.0f);
            atomicAdd(&base[0], (unsigned long long)xi
                                | ((unsigned long long)yi << 17)
                                | ((unsigned long long)zi << 34)
                                | (1ull << 48));
            atomicAdd(&base[1], (unsigned long long)q0
                                | ((unsigned long long)q1 << 21)
                                | ((unsigned long long)q2 << 42));
            atomicAdd(&base[2], (unsigned long long)r0
                                | ((unsigned long long)r1 << 21)
                                | ((unsigned long long)r2 << 42));
            if (ca[k] != 0) {   // centers are ~1-per-volume rare: direct global
                int bi = b * NSG + id;
                atomicAdd(&g_acc[OFF_CCNT + bi], 1.0f);
                atomicAdd(&g_acc[OFF_CXYZ + bi * 3 + 0], (float)xi * (1.0f / 1023.0f));
                atomicAdd(&g_acc[OFF_CXYZ + bi * 3 + 1], (float)yi * (1.0f / 1023.0f));
                atomicAdd(&g_acc[OFF_CXYZ + bi * 3 + 2], (float)zi * (1.0f / 31.0f));
            }
        }
    }
    __syncthreads();

    // decode per-warp packs -> block-level float accumulation
    if (lane < NSG) {
        unsigned long long pA = wacc[warp][lane][0];
        unsigned long long pB = wacc[warp][lane][1];
        unsigned long long pC = wacc[warp][lane][2];
        float cnt = (float)(unsigned)(pA >> 48);
        float xs = (float)(unsigned)(pA & 0x1FFFFu) * (1.0f / 1023.0f);
        float ys = (float)(unsigned)((pA >> 17) & 0x1FFFFu) * (1.0f / 1023.0f);
        float zs = (float)(unsigned)((pA >> 34) & 0x3FFFu) * (1.0f / 31.0f);
        float s0s = (float)(unsigned)(pB & 0x1FFFFFu) * (1.0f / 256.0f) - 16.0f * cnt;
        float s1s = (float)(unsigned)((pB >> 21) & 0x1FFFFFu) * (1.0f / 256.0f) - 16.0f * cnt;
        float s2s = (float)(unsigned)((pB >> 42) & 0x1FFFFFu) * (1.0f / 256.0f) - 16.0f * cnt;
        float r0s = (float)(unsigned)(pC & 0x1FFFFFu) * (1.0f / 32.0f);
        float r1s = (float)(unsigned)((pC >> 21) & 0x1FFFFFu) * (1.0f / 32.0f);
        float r2s = (float)(unsigned)((pC >> 42) & 0x1FFFFFu) * (1.0f / 32.0f);
        float* d = sm + lane * 10;
        atomicAdd(d + 0, cnt);
        atomicAdd(d + 1, s0s);
        atomicAdd(d + 2, s1s);
        atomicAdd(d + 3, s2s);
        atomicAdd(d + 4, r0s);
        atomicAdd(d + 5, r1s);
        atomicAdd(d + 6, r2s);
        atomicAdd(d + 7, xs);
        atomicAdd(d + 8, ys);
        atomicAdd(d + 9, zs);
    }
    __syncthreads();
    if (tid < NSG * 10) {
        int id = tid / 10, f = tid % 10;
        float vsm = sm[tid];
        if (vsm != 0.0f) {
            int bi = b * NSG + id;
            float* dst;
            if (f == 0)      dst = &g_acc[OFF_CNT  + bi];
            else if (f < 4)  dst = &g_acc[OFF_SSUM + bi * 3 + (f - 1)];
            else if (f < 7)  dst = &g_acc[OFF_SSQ  + bi * 3 + (f - 4)];
            else             dst = &g_acc[OFF_XYZ  + bi * 3 + (f - 7)];
            atomicAdd(dst, vsm);
        }
    }
}

// ---------------------------------------------------------------- params (+ zero stats accumulators)
__global__ void k_params() {
    int t = threadIdx.x;
    if (t >= BB * NSG) return;
    int b = t / NSG, id = t % NSG;
    float cnt = g_acc[OFF_CNT + t];
    float safe = fmaxf(cnt, 1.0f);
    float varsum = 0.0f;
    float m[3];
    float xyz[3], cxyz[3];
#pragma unroll
    for (int c = 0; c < 3; c++) {
        float ss = g_acc[OFF_SSUM + t * 3 + c];
        float sq = g_acc[OFF_SSQ + t * 3 + c];
        float mm = ss / safe;
        m[c] = mm;
        varsum += (sq - 2.0f * mm * ss + cnt * mm * mm) / safe;
        xyz[c] = g_acc[OFF_XYZ + t * 3 + c];
        cxyz[c] = g_acc[OFF_CXYZ + t * 3 + c];
    }
    float ccnt = g_acc[OFF_CCNT + t];
    // zero for next graph replay
    g_acc[OFF_CNT + t] = 0.0f;
    g_acc[OFF_CCNT + t] = 0.0f;
#pragma unroll
    for (int c = 0; c < 3; c++) {
        g_acc[OFF_SSUM + t * 3 + c] = 0.0f;
        g_acc[OFF_SSQ + t * 3 + c] = 0.0f;
        g_acc[OFF_XYZ + t * 3 + c] = 0.0f;
        g_acc[OFF_CXYZ + t * 3 + c] = 0.0f;
    }
    if (id >= 1) {
        atomicAdd(&g_acc[OFF_VAR + b], varsum * (1.0f / (3.0f * NI)));
        bool one = (ccnt == 1.0f);
        int p = (b * NI + (id - 1)) * 3;
#pragma unroll
        for (int c = 0; c < 3; c++) {
            float cen = one ? cxyz[c] : xyz[c] / safe;
            g_acc[OFF_CEN + p + c] = cen;
            g_acc[OFF_S + p + c] = expf(10.0f * m[c]);
        }
    }
}

// ---------------------------------------------------------------- dist + histogram + seed loss
// grid (1024, BB, 4), 256 thr, grid-stride scalar loop (8 iters, 1 voxel/iter).
// blockIdx.z selects 4 of 16 instances. u32 RED, fg/bg split arrays.
__global__ void __launch_bounds__(256) k_dist(const float* __restrict__ pred,
                                              const int* __restrict__ inst,
                                              const int* __restrict__ lab) {
    int b = blockIdx.y;
    int quart = blockIdx.z;          // instances [quart*4, quart*4+4)
    int nbase = quart * 4;

    float c0[4], c1[4], c2[4], s0[4], s1[4], s2[4];
#pragma unroll
    for (int j = 0; j < 4; j++) {
        int p = (b * NI + nbase + j) * 3;
        s0[j] = g_acc[OFF_S + p];
        s1[j] = g_acc[OFF_S + p + 1];
        s2[j] = g_acc[OFF_S + p + 2];
        c0[j] = g_acc[OFF_CEN + p];
        c1[j] = g_acc[OFF_CEN + p + 1];
        c2[j] = g_acc[OFF_CEN + p + 2];
    }

    const float* pb = pred + (size_t)b * NCH * VV;
    const int* ib = inst + (size_t)b * VV;
    const int* lb = lab + (size_t)b * VV;
    unsigned* hfg = g_hfg + (size_t)b * NI * NBINS * SLOTS;
    unsigned* hbg = g_hbg + (size_t)b * NI * NBINS * SLOTS;
    int slot = threadIdx.x & (SLOTS - 1);

    float accbg = 0.0f, accfg = 0.0f;

    for (int v = blockIdx.x * 256 + threadIdx.x; v < VV; v += 1024 * 256) {
        float x = (float)(v & 255) * (1.0f / 1023.0f);
        float y = (float)((v >> 8) & 255) * (1.0f / 1023.0f);
        float z = (float)(v >> 16) * (1.0f / 31.0f);
        float e0 = fast_tanh(pb[v]) + x;
        float e1 = fast_tanh(pb[VV + v]) + y;
        float e2 = fast_tanh(pb[2 * VV + v]) + z;
        int id = ib[v];
        float down = 0.0f;
#pragma unroll
        for (int j = 0; j < 4; j++) {
            int n = nbase + j;
            float dx = e0 - c0[j], dy = e1 - c1[j], dz = e2 - c2[j];
            float arg = s0[j] * dx * dx + s1[j] * dy * dy + s2[j] * dz * dz;
            float d = __expf(-arg);
            bool fg = (id == n + 1);
            if (fg) down = d;
            float e = fg ? fmaf(-2.0f, d, 2.0f) : 2.0f * d;
            int bin = (int)(e * (NBINS * 0.5f));
            if (bin > NBINS - 1) bin = NBINS - 1;
            unsigned* arr = fg ? hfg : hbg;
            atomicAdd(&arr[(((n * NBINS) + bin) << 2) | slot], 1u);
        }
        bool own = (id > nbase && id <= nbase + 4);
        bool bg = (quart == 0) && (lb[v] == 0);
        if (own | bg) {
            float sd = 1.0f / (1.0f + __expf(-pb[6 * VV + v]));
            if (own) {
                float t = sd - down;
                accfg += t * t;
            }
            if (bg) accbg += sd * sd;
        }
    }

    __shared__ float r1[256], r2[256];
    int t = threadIdx.x;
    r1[t] = accbg;
    r2[t] = accfg;
    __syncthreads();
    for (int s = 128; s > 0; s >>= 1) {
        if (t < s) { r1[t] += r1[t + s]; r2[t] += r2[t + s]; }
        __syncthreads();
    }
    if (t == 0) {
        if (quart == 0) atomicAdd(&g_acc[OFF_SBG + b], r1[0]);
        atomicAdd(&g_acc[OFF_SFG + b], r2[0]);
    }
}

// ---------------------------------------------------------------- lovasz from histogram (+ self-wipe)
// one block per (b,n); 1024 threads; CH=4 bins/thread; shfl-based prefix scan
__global__ void __launch_bounds__(1024) k_lovasz() {
    int bn = blockIdx.x;       // b*16 + n
    int b = bn >> 4;
    unsigned* HF = g_hfg + (size_t)bn * NBINS * SLOTS;
    unsigned* HB = g_hbg + (size_t)bn * NBINS * SLOTS;
    const int CH = NBINS / 1024;  // 4
    int t = threadIdx.x;
    int lane = t & 31, warp = t >> 5;

    // load my bins (descending error order: rank r = t*CH+i, bin = NBINS-1-r)
    float fA[CH], bA[CH];
    float locF = 0.0f, locB = 0.0f;
#pragma unroll
    for (int i = 0; i < CH; i++) {
        int bin = NBINS - 1 - (t * CH + i);
        uint4 vf = *(uint4*)&HF[bin << 2];
        uint4 vb = *(uint4*)&HB[bin << 2];
        fA[i] = (float)(vf.x + vf.y + vf.z + vf.w);
        bA[i] = (float)(vb.x + vb.y + vb.z + vb.w);
        locF += fA[i];
        locB += bA[i];
        // zero for next replay
        *(uint4*)&HF[bin << 2] = make_uint4(0, 0, 0, 0);
        *(uint4*)&HB[bin << 2] = make_uint4(0, 0, 0, 0);
    }

    // warp-level inclusive scan of (locF, locB) in thread order
    float incF = locF, incB = locB;
#pragma unroll
    for (int d = 1; d < 32; d <<= 1) {
        float vF = __shfl_up_sync(0xffffffffu, incF, d);
        float vB = __shfl_up_sync(0xffffffffu, incB, d);
        if (lane >= d) { incF += vF; incB += vB; }
    }
    __shared__ float wF[32], wB[32];
    __shared__ float sred[1024];
    __shared__ int sMinR;
    if (t == 0) sMinR = NBINS;
    if (lane == 31) { wF[warp] = incF; wB[warp] = incB; }
    __syncthreads();
    float offF = 0.0f, offB = 0.0f, G = 0.0f;
#pragma unroll
    for (int w = 0; w < 32; w++) {
        float f = wF[w];
        if (w < warp) { offF += f; offB += wB[w]; }
        G += f;
    }
    float P = offF + incF - locF;   // exclusive prefix (fg)
    float Q = offB + incB - locB;   // exclusive prefix (bg)

    float contrib = 0.0f;
    if (G > 0.0f) {
#pragma unroll
        for (int i = 0; i < CH; i++) {
            float f = fA[i], bb = bA[i];
            if (f > 0.0f || bb > 0.0f) {
                int bin = NBINS - 1 - (t * CH + i);
                float e = ((float)bin + 0.5f) * (2.0f / NBINS);
                float gq = G + Q;
                float num = (G - P) * bb + f * gq;   // cancellation-free jacc delta
                float den = gq * (gq + bb);
                contrib += e * num / den;
                P += f;
                Q += bb;
            }
        }
    } else {  // degenerate: no fg voxels -> loss = max error present
#pragma unroll
        for (int i = 0; i < CH; i++) {
            if (fA[i] > 0.0f || bA[i] > 0.0f) {
                atomicMin(&sMinR, t * CH + i);
                break;
            }
        }
    }
    sred[t] = contrib;
    __syncthreads();
    for (int s2 = 512; s2 > 0; s2 >>= 1) {
        if (t < s2) sred[t] += sred[t + s2];
        __syncthreads();
    }
    if (t == 0) {
        float total = sred[0];
        if (G <= 0.0f && sMinR < NBINS)
            total = ((float)(NBINS - 1 - sMinR) + 0.5f) * (2.0f / NBINS);
        atomicAdd(&g_acc[OFF_ILOSS + b], total);
    }
}

// ---------------------------------------------------------------- final combine (+ zero loss accumulators)
__global__ void k_final(float* out) {
    if (threadIdx.x == 0 && blockIdx.x == 0) {
        float r = 0.0f;
        for (int b = 0; b < BB; b++) {
            float il = g_acc[OFF_ILOSS + b] * (1.0f / NI);        // instance loss (W=1)
            float vl = g_acc[OFF_VAR + b];                        // var loss
            float sl = (g_acc[OFF_SBG + b] + 10.0f * g_acc[OFF_SFG + b]) * (1.0f / VV);
            r += il + 10.0f * vl + sl;
            g_acc[OFF_ILOSS + b] = 0.0f;
            g_acc[OFF_VAR + b] = 0.0f;
            g_acc[OFF_SBG + b] = 0.0f;
            g_acc[OFF_SFG + b] = 0.0f;
        }
        out[0] = r * (1.0f / BB);
    }
}

// ---------------------------------------------------------------- launch
extern "C" void kernel_launch(void* const* d_in, const int* in_sizes, int n_in,
                              void* d_out, int out_size) {
    const float* pred = (const float*)d_in[0];
    const int* inst = (const int*)d_in[1];
    const int* lab = (const int*)d_in[2];
    const int* cent = (const int*)d_in[3];

    {
        dim3 g(1024, BB);
        k_stats<<<g, 256>>>(pred, inst, cent);
    }
    k_params<<<1, 64>>>();
    {
        dim3 g(1024, BB, 4);
        k_dist<<<g, 256>>>(pred, inst, lab);
    }
    k_lovasz<<<BB * NI, 1024>>>();
    k_final<<<1, 1>>>((float*)d_out);
}

// round 7
// speedup vs baseline: 1.2284x; 1.2284x over previous
#include <cuda_runtime.h>

#define BB 2
#define NCH 7
#define VV 2097152          // 32*256*256
#define NI 16
#define NSG 17
#define NBINS 2048

// accumulator layout (floats)
#define OFF_CNT   0          // BB*NSG
#define OFF_SSUM  34         // BB*NSG*3
#define OFF_SSQ   136
#define OFF_XYZ   238
#define OFF_CCNT  340
#define OFF_CXYZ  374
#define OFF_VAR   476        // BB
#define OFF_SBG   478
#define OFF_SFG   480
#define OFF_ILOSS 482
#define OFF_S     484        // BB*NI*3
#define OFF_CEN   580        // BB*NI*3
#define ACC_N     676

__device__ float g_acc[ACC_N];                  // zero-init; self-cleaning
__device__ unsigned g_hfg[BB * NI * NBINS];     // 128KB fg counts
__device__ unsigned g_hbg[BB * NI * NBINS];     // 128KB bg counts

__device__ __forceinline__ float fast_tanh(float x) {
    float r;
    asm("tanh.approx.f32 %0, %1;" : "=f"(r) : "f"(x));
    return r;
}

// ---------------------------------------------------------------- stats
// Per-warp fixed-point packed accumulators (3 u64 per id), exact/bounded for
// exactly 256 voxels per warp. grid (1024, BB), 256 thr, 8 voxels/thread.
__global__ void __launch_bounds__(256) k_stats(const float* __restrict__ pred,
                                               const int* __restrict__ inst,
                                               const int* __restrict__ cent) {
    int b = blockIdx.y;
    __shared__ unsigned long long wacc[8][NSG][3];
    __shared__ float sm[NSG * 10];
    int tid = threadIdx.x;
    int warp = tid >> 5, lane = tid & 31;

    for (int j = tid; j < 8 * NSG * 3; j += 256)
        ((unsigned long long*)wacc)[j] = 0ull;
    for (int j = tid; j < NSG * 10; j += 256) sm[j] = 0.0f;
    __syncthreads();

    const float* sig = pred + ((size_t)b * NCH + 3) * VV;
    const int* ib = inst + (size_t)b * VV;
    const int* cb = cent + (size_t)b * VV;

    int v0 = (blockIdx.x * 256 + tid) * 8;
#pragma unroll
    for (int g = 0; g < 2; g++) {
        int vb = v0 + g * 4;
        float4 f0 = *(const float4*)(sig + vb);
        float4 f1 = *(const float4*)(sig + VV + vb);
        float4 f2 = *(const float4*)(sig + 2 * VV + vb);
        int4 iv = *(const int4*)(ib + vb);
        int4 cv = *(const int4*)(cb + vb);
        float a0[4] = {f0.x, f0.y, f0.z, f0.w};
        float a1[4] = {f1.x, f1.y, f1.z, f1.w};
        float a2[4] = {f2.x, f2.y, f2.z, f2.w};
        int ia[4] = {iv.x, iv.y, iv.z, iv.w};
        int ca[4] = {cv.x, cv.y, cv.z, cv.w};
#pragma unroll
        for (int k = 0; k < 4; k++) {
            int v = vb + k;
            int id = ia[k];
            float s0 = fminf(fmaxf(a0[k], -15.5f), 15.5f);
            float s1 = fminf(fmaxf(a1[k], -15.5f), 15.5f);
            float s2 = fminf(fmaxf(a2[k], -15.5f), 15.5f);
            unsigned xi = v & 255;
            unsigned yi = (v >> 8) & 255;
            unsigned zi = (unsigned)v >> 16;
            unsigned long long* base = wacc[warp][id];
            unsigned q0 = __float2uint_rn((s0 + 16.0f) * 256.0f);
            unsigned q1 = __float2uint_rn((s1 + 16.0f) * 256.0f);
            unsigned q2 = __float2uint_rn((s2 + 16.0f) * 256.0f);
            unsigned r0 = __float2uint_rn(s0 * s0 * 32.0f);
            unsigned r1 = __float2uint_rn(s1 * s1 * 32.0f);
            unsigned r2 = __float2uint_rn(s2 * s2 * 32.0f);
            atomicAdd(&base[0], (unsigned long long)xi
                                | ((unsigned long long)yi << 17)
                                | ((unsigned long long)zi << 34)
                                | (1ull << 48));
            atomicAdd(&base[1], (unsigned long long)q0
                                | ((unsigned long long)q1 << 21)
                                | ((unsigned long long)q2 << 42));
            atomicAdd(&base[2], (unsigned long long)r0
                                | ((unsigned long long)r1 << 21)
                                | ((unsigned long long)r2 << 42));
            if (ca[k] != 0) {   // centers are ~1-per-volume rare: direct global
                int bi = b * NSG + id;
                atomicAdd(&g_acc[OFF_CCNT + bi], 1.0f);
                atomicAdd(&g_acc[OFF_CXYZ + bi * 3 + 0], (float)xi * (1.0f / 1023.0f));
                atomicAdd(&g_acc[OFF_CXYZ + bi * 3 + 1], (float)yi * (1.0f / 1023.0f));
                atomicAdd(&g_acc[OFF_CXYZ + bi * 3 + 2], (float)zi * (1.0f / 31.0f));
            }
        }
    }
    __syncthreads();

    // decode per-warp packs -> block-level float accumulation
    if (lane < NSG) {
        unsigned long long pA = wacc[warp][lane][0];
        unsigned long long pB = wacc[warp][lane][1];
        unsigned long long pC = wacc[warp][lane][2];
        float cnt = (float)(unsigned)(pA >> 48);
        float xs = (float)(unsigned)(pA & 0x1FFFFu) * (1.0f / 1023.0f);
        float ys = (float)(unsigned)((pA >> 17) & 0x1FFFFu) * (1.0f / 1023.0f);
        float zs = (float)(unsigned)((pA >> 34) & 0x3FFFu) * (1.0f / 31.0f);
        float s0s = (float)(unsigned)(pB & 0x1FFFFFu) * (1.0f / 256.0f) - 16.0f * cnt;
        float s1s = (float)(unsigned)((pB >> 21) & 0x1FFFFFu) * (1.0f / 256.0f) - 16.0f * cnt;
        float s2s = (float)(unsigned)((pB >> 42) & 0x1FFFFFu) * (1.0f / 256.0f) - 16.0f * cnt;
        float r0s = (float)(unsigned)(pC & 0x1FFFFFu) * (1.0f / 32.0f);
        float r1s = (float)(unsigned)((pC >> 21) & 0x1FFFFFu) * (1.0f / 32.0f);
        float r2s = (float)(unsigned)((pC >> 42) & 0x1FFFFFu) * (1.0f / 32.0f);
        float* d = sm + lane * 10;
        atomicAdd(d + 0, cnt);
        atomicAdd(d + 1, s0s);
        atomicAdd(d + 2, s1s);
        atomicAdd(d + 3, s2s);
        atomicAdd(d + 4, r0s);
        atomicAdd(d + 5, r1s);
        atomicAdd(d + 6, r2s);
        atomicAdd(d + 7, xs);
        atomicAdd(d + 8, ys);
        atomicAdd(d + 9, zs);
    }
    __syncthreads();
    if (tid < NSG * 10) {
        int id = tid / 10, f = tid % 10;
        float vsm = sm[tid];
        if (vsm != 0.0f) {
            int bi = b * NSG + id;
            float* dst;
            if (f == 0)      dst = &g_acc[OFF_CNT  + bi];
            else if (f < 4)  dst = &g_acc[OFF_SSUM + bi * 3 + (f - 1)];
            else if (f < 7)  dst = &g_acc[OFF_SSQ  + bi * 3 + (f - 4)];
            else             dst = &g_acc[OFF_XYZ  + bi * 3 + (f - 7)];
            atomicAdd(dst, vsm);
        }
    }
}

// ---------------------------------------------------------------- params (+ zero stats accumulators)
__global__ void k_params() {
    int t = threadIdx.x;
    if (t >= BB * NSG) return;
    int b = t / NSG, id = t % NSG;
    float cnt = g_acc[OFF_CNT + t];
    float safe = fmaxf(cnt, 1.0f);
    float varsum = 0.0f;
    float m[3];
    float xyz[3], cxyz[3];
#pragma unroll
    for (int c = 0; c < 3; c++) {
        float ss = g_acc[OFF_SSUM + t * 3 + c];
        float sq = g_acc[OFF_SSQ + t * 3 + c];
        float mm = ss / safe;
        m[c] = mm;
        varsum += (sq - 2.0f * mm * ss + cnt * mm * mm) / safe;
        xyz[c] = g_acc[OFF_XYZ + t * 3 + c];
        cxyz[c] = g_acc[OFF_CXYZ + t * 3 + c];
    }
    float ccnt = g_acc[OFF_CCNT + t];
    // zero for next graph replay
    g_acc[OFF_CNT + t] = 0.0f;
    g_acc[OFF_CCNT + t] = 0.0f;
#pragma unroll
    for (int c = 0; c < 3; c++) {
        g_acc[OFF_SSUM + t * 3 + c] = 0.0f;
        g_acc[OFF_SSQ + t * 3 + c] = 0.0f;
        g_acc[OFF_XYZ + t * 3 + c] = 0.0f;
        g_acc[OFF_CXYZ + t * 3 + c] = 0.0f;
    }
    if (id >= 1) {
        atomicAdd(&g_acc[OFF_VAR + b], varsum * (1.0f / (3.0f * NI)));
        bool one = (ccnt == 1.0f);
        int p = (b * NI + (id - 1)) * 3;
#pragma unroll
        for (int c = 0; c < 3; c++) {
            float cen = one ? cxyz[c] : xyz[c] / safe;
            g_acc[OFF_CEN + p + c] = cen;
            g_acc[OFF_S + p + c] = expf(10.0f * m[c]);
        }
    }
}

// ---------------------------------------------------------------- dist + SMEM histogram + seed loss
// grid (32, BB, 4), 256 thr. Each block: 65536 voxels (256 iters), private
// 4-inst x 2048-bin smem bg histogram (32KB), single flush at the end.
// fg increments (1/17 of pairs) go straight to global RED.
__global__ void __launch_bounds__(256) k_dist(const float* __restrict__ pred,
                                              const int* __restrict__ inst,
                                              const int* __restrict__ lab) {
    __shared__ unsigned shist[4 * NBINS];     // 32KB
    __shared__ float r1[256], r2[256];
    int b = blockIdx.y;
    int quart = blockIdx.z;          // instances [quart*4, quart*4+4)
    int nbase = quart * 4;

    float c0[4], c1[4], c2[4], s0[4], s1[4], s2[4];
#pragma unroll
    for (int j = 0; j < 4; j++) {
        int p = (b * NI + nbase + j) * 3;
        s0[j] = g_acc[OFF_S + p];
        s1[j] = g_acc[OFF_S + p + 1];
        s2[j] = g_acc[OFF_S + p + 2];
        c0[j] = g_acc[OFF_CEN + p];
        c1[j] = g_acc[OFF_CEN + p + 1];
        c2[j] = g_acc[OFF_CEN + p + 2];
    }

    for (int i = threadIdx.x; i < 4 * NBINS; i += 256) shist[i] = 0u;
    __syncthreads();

    const float* pb = pred + (size_t)b * NCH * VV;
    const int* ib = inst + (size_t)b * VV;
    const int* lb = lab + (size_t)b * VV;
    unsigned* hfg = g_hfg + (size_t)b * NI * NBINS;

    float accbg = 0.0f, accfg = 0.0f;

    for (int v = blockIdx.x * 256 + threadIdx.x; v < VV; v += 32 * 256) {
        float x = (float)(v & 255) * (1.0f / 1023.0f);
        float y = (float)((v >> 8) & 255) * (1.0f / 1023.0f);
        float z = (float)(v >> 16) * (1.0f / 31.0f);
        float e0 = fast_tanh(pb[v]) + x;
        float e1 = fast_tanh(pb[VV + v]) + y;
        float e2 = fast_tanh(pb[2 * VV + v]) + z;
        int id = ib[v];
        float down = 0.0f;
#pragma unroll
        for (int j = 0; j < 4; j++) {
            int n = nbase + j;
            float dx = e0 - c0[j], dy = e1 - c1[j], dz = e2 - c2[j];
            float arg = s0[j] * dx * dx + s1[j] * dy * dy + s2[j] * dz * dz;
            float d = __expf(-arg);
            bool fg = (id == n + 1);
            if (fg) down = d;
            float e = fg ? fmaf(-2.0f, d, 2.0f) : 2.0f * d;
            int bin = (int)(e * (NBINS * 0.5f));
            if (bin > NBINS - 1) bin = NBINS - 1;
            if (fg) atomicAdd(&hfg[n * NBINS + bin], 1u);
            else    atomicAdd(&shist[j * NBINS + bin], 1u);
        }
        bool own = (id > nbase && id <= nbase + 4);
        bool bg = (quart == 0) && (lb[v] == 0);
        if (own | bg) {
            float sd = 1.0f / (1.0f + __expf(-pb[6 * VV + v]));
            if (own) {
                float t = sd - down;
                accfg += t * t;
            }
            if (bg) accbg += sd * sd;
        }
    }

    __syncthreads();
    // flush bg histogram: one pre-aggregated RED per nonzero bin
    unsigned* dstbg = g_hbg + (size_t)(b * NI + nbase) * NBINS;
    for (int i = threadIdx.x; i < 4 * NBINS; i += 256) {
        unsigned c = shist[i];
        if (c) atomicAdd(&dstbg[i], c);
    }

    int t = threadIdx.x;
    r1[t] = accbg;
    r2[t] = accfg;
    __syncthreads();
    for (int s = 128; s > 0; s >>= 1) {
        if (t < s) { r1[t] += r1[t + s]; r2[t] += r2[t + s]; }
        __syncthreads();
    }
    if (t == 0) {
        if (quart == 0) atomicAdd(&g_acc[OFF_SBG + b], r1[0]);
        atomicAdd(&g_acc[OFF_SFG + b], r2[0]);
    }
}

// ---------------------------------------------------------------- lovasz from histogram (+ self-wipe)
// one block per (b,n); 1024 threads; CH=2 bins/thread; shfl-based prefix scan
__global__ void __launch_bounds__(1024) k_lovasz() {
    int bn = blockIdx.x;       // b*16 + n
    int b = bn >> 4;
    unsigned* HF = g_hfg + (size_t)bn * NBINS;
    unsigned* HB = g_hbg + (size_t)bn * NBINS;
    const int CH = NBINS / 1024;  // 2
    int t = threadIdx.x;
    int lane = t & 31, warp = t >> 5;

    // load my bins (descending error order: rank r = t*CH+i, bin = NBINS-1-r)
    float fA[CH], bA[CH];
    float locF = 0.0f, locB = 0.0f;
#pragma unroll
    for (int i = 0; i < CH; i++) {
        int bin = NBINS - 1 - (t * CH + i);
        fA[i] = (float)HF[bin];
        bA[i] = (float)HB[bin];
        locF += fA[i];
        locB += bA[i];
        HF[bin] = 0u;     // self-wipe for next replay
        HB[bin] = 0u;
    }

    // warp-level inclusive scan of (locF, locB) in thread order
    float incF = locF, incB = locB;
#pragma unroll
    for (int d = 1; d < 32; d <<= 1) {
        float vF = __shfl_up_sync(0xffffffffu, incF, d);
        float vB = __shfl_up_sync(0xffffffffu, incB, d);
        if (lane >= d) { incF += vF; incB += vB; }
    }
    __shared__ float wF[32], wB[32];
    __shared__ float sred[1024];
    __shared__ int sMinR;
    if (t == 0) sMinR = NBINS;
    if (lane == 31) { wF[warp] = incF; wB[warp] = incB; }
    __syncthreads();
    float offF = 0.0f, offB = 0.0f, G = 0.0f;
#pragma unroll
    for (int w = 0; w < 32; w++) {
        float f = wF[w];
        if (w < warp) { offF += f; offB += wB[w]; }
        G += f;
    }
    float P = offF + incF - locF;   // exclusive prefix (fg)
    float Q = offB + incB - locB;   // exclusive prefix (bg)

    float contrib = 0.0f;
    if (G > 0.0f) {
#pragma unroll
        for (int i = 0; i < CH; i++) {
            float f = fA[i], bb = bA[i];
            if (f > 0.0f || bb > 0.0f) {
                int bin = NBINS - 1 - (t * CH + i);
                float e = ((float)bin + 0.5f) * (2.0f / NBINS);
                float gq = G + Q;
                float num = (G - P) * bb + f * gq;   // cancellation-free jacc delta
                float den = gq * (gq + bb);
                contrib += e * num / den;
                P += f;
                Q += bb;
            }
        }
    } else {  // degenerate: no fg voxels -> loss = max error present
#pragma unroll
        for (int i = 0; i < CH; i++) {
            if (fA[i] > 0.0f || bA[i] > 0.0f) {
                atomicMin(&sMinR, t * CH + i);
                break;
            }
        }
    }
    sred[t] = contrib;
    __syncthreads();
    for (int s2 = 512; s2 > 0; s2 >>= 1) {
        if (t < s2) sred[t] += sred[t + s2];
        __syncthreads();
    }
    if (t == 0) {
        float total = sred[0];
        if (G <= 0.0f && sMinR < NBINS)
            total = ((float)(NBINS - 1 - sMinR) + 0.5f) * (2.0f / NBINS);
        atomicAdd(&g_acc[OFF_ILOSS + b], total);
    }
}

// ---------------------------------------------------------------- final combine (+ zero loss accumulators)
__global__ void k_final(float* out) {
    if (threadIdx.x == 0 && blockIdx.x == 0) {
        float r = 0.0f;
        for (int b = 0; b < BB; b++) {
            float il = g_acc[OFF_ILOSS + b] * (1.0f / NI);        // instance loss (W=1)
            float vl = g_acc[OFF_VAR + b];                        // var loss
            float sl = (g_acc[OFF_SBG + b] + 10.0f * g_acc[OFF_SFG + b]) * (1.0f / VV);
            r += il + 10.0f * vl + sl;
            g_acc[OFF_ILOSS + b] = 0.0f;
            g_acc[OFF_VAR + b] = 0.0f;
            g_acc[OFF_SBG + b] = 0.0f;
            g_acc[OFF_SFG + b] = 0.0f;
        }
        out[0] = r * (1.0f / BB);
    }
}

// ---------------------------------------------------------------- launch
extern "C" void kernel_launch(void* const* d_in, const int* in_sizes, int n_in,
                              void* d_out, int out_size) {
    const float* pred = (const float*)d_in[0];
    const int* inst = (const int*)d_in[1];
    const int* lab = (const int*)d_in[2];
    const int* cent = (const int*)d_in[3];

    {
        dim3 g(1024, BB);
        k_stats<<<g, 256>>>(pred, inst, cent);
    }
    k_params<<<1, 64>>>();
    {
        dim3 g(32, BB, 4);
        k_dist<<<g, 256>>>(pred, inst, lab);
    }
    k_lovasz<<<BB * NI, 1024>>>();
    k_final<<<1, 1>>>((float*)d_out);
}

// round 8
// speedup vs baseline: 2.1735x; 1.7694x over previous
#include <cuda_runtime.h>

#define BB 2
#define NCH 7
#define VV 2097152          // 32*256*256
#define NI 16
#define NSG 17
#define NBINS 2048
#define DGRID 128           // k_dist grid.x

// accumulator layout (floats)
#define OFF_CNT   0          // BB*NSG
#define OFF_SSUM  34         // BB*NSG*3
#define OFF_SSQ   136
#define OFF_XYZ   238
#define OFF_CCNT  340
#define OFF_CXYZ  374
#define OFF_VAR   476        // BB
#define OFF_SBG   478
#define OFF_SFG   480
#define OFF_ILOSS 482
#define OFF_S     484        // BB*NI*3
#define OFF_CEN   580        // BB*NI*3
#define ACC_N     676

__device__ float g_acc[ACC_N];                  // zero-init; self-cleaning
__device__ unsigned g_hfg[BB * NI * NBINS];     // 128KB fg counts
__device__ unsigned g_hbg[BB * NI * NBINS];     // 128KB bg counts

__device__ __forceinline__ float fast_tanh(float x) {
    float r;
    asm("tanh.approx.f32 %0, %1;" : "=f"(r) : "f"(x));
    return r;
}

// ---------------------------------------------------------------- stats
// Per-warp fixed-point packed accumulators (3 u64 per id), exact/bounded for
// exactly 256 voxels per warp. grid (1024, BB), 256 thr, 8 voxels/thread.
__global__ void __launch_bounds__(256) k_stats(const float* __restrict__ pred,
                                               const int* __restrict__ inst,
                                               const int* __restrict__ cent) {
    int b = blockIdx.y;
    __shared__ unsigned long long wacc[8][NSG][3];
    __shared__ float sm[NSG * 10];
    int tid = threadIdx.x;
    int warp = tid >> 5, lane = tid & 31;

    for (int j = tid; j < 8 * NSG * 3; j += 256)
        ((unsigned long long*)wacc)[j] = 0ull;
    for (int j = tid; j < NSG * 10; j += 256) sm[j] = 0.0f;
    __syncthreads();

    const float* sig = pred + ((size_t)b * NCH + 3) * VV;
    const int* ib = inst + (size_t)b * VV;
    const int* cb = cent + (size_t)b * VV;

    int v0 = (blockIdx.x * 256 + tid) * 8;
#pragma unroll
    for (int g = 0; g < 2; g++) {
        int vb = v0 + g * 4;
        float4 f0 = *(const float4*)(sig + vb);
        float4 f1 = *(const float4*)(sig + VV + vb);
        float4 f2 = *(const float4*)(sig + 2 * VV + vb);
        int4 iv = *(const int4*)(ib + vb);
        int4 cv = *(const int4*)(cb + vb);
        float a0[4] = {f0.x, f0.y, f0.z, f0.w};
        float a1[4] = {f1.x, f1.y, f1.z, f1.w};
        float a2[4] = {f2.x, f2.y, f2.z, f2.w};
        int ia[4] = {iv.x, iv.y, iv.z, iv.w};
        int ca[4] = {cv.x, cv.y, cv.z, cv.w};
#pragma unroll
        for (int k = 0; k < 4; k++) {
            int v = vb + k;
            int id = ia[k];
            float s0 = fminf(fmaxf(a0[k], -15.5f), 15.5f);
            float s1 = fminf(fmaxf(a1[k], -15.5f), 15.5f);
            float s2 = fminf(fmaxf(a2[k], -15.5f), 15.5f);
            unsigned xi = v & 255;
            unsigned yi = (v >> 8) & 255;
            unsigned zi = (unsigned)v >> 16;
            unsigned long long* base = wacc[warp][id];
            unsigned q0 = __float2uint_rn((s0 + 16.0f) * 256.0f);
            unsigned q1 = __float2uint_rn((s1 + 16.0f) * 256.0f);
            unsigned q2 = __float2uint_rn((s2 + 16.0f) * 256.0f);
            unsigned r0 = __float2uint_rn(s0 * s0 * 32.0f);
            unsigned r1 = __float2uint_rn(s1 * s1 * 32.0f);
            unsigned r2 = __float2uint_rn(s2 * s2 * 32.0f);
            atomicAdd(&base[0], (unsigned long long)xi
                                | ((unsigned long long)yi << 17)
                                | ((unsigned long long)zi << 34)
                                | (1ull << 48));
            atomicAdd(&base[1], (unsigned long long)q0
                                | ((unsigned long long)q1 << 21)
                                | ((unsigned long long)q2 << 42));
            atomicAdd(&base[2], (unsigned long long)r0
                                | ((unsigned long long)r1 << 21)
                                | ((unsigned long long)r2 << 42));
            if (ca[k] != 0) {   // centers are ~1-per-volume rare: direct global
                int bi = b * NSG + id;
                atomicAdd(&g_acc[OFF_CCNT + bi], 1.0f);
                atomicAdd(&g_acc[OFF_CXYZ + bi * 3 + 0], (float)xi * (1.0f / 1023.0f));
                atomicAdd(&g_acc[OFF_CXYZ + bi * 3 + 1], (float)yi * (1.0f / 1023.0f));
                atomicAdd(&g_acc[OFF_CXYZ + bi * 3 + 2], (float)zi * (1.0f / 31.0f));
            }
        }
    }
    __syncthreads();

    // decode per-warp packs -> block-level float accumulation
    if (lane < NSG) {
        unsigned long long pA = wacc[warp][lane][0];
        unsigned long long pB = wacc[warp][lane][1];
        unsigned long long pC = wacc[warp][lane][2];
        float cnt = (float)(unsigned)(pA >> 48);
        float xs = (float)(unsigned)(pA & 0x1FFFFu) * (1.0f / 1023.0f);
        float ys = (float)(unsigned)((pA >> 17) & 0x1FFFFu) * (1.0f / 1023.0f);
        float zs = (float)(unsigned)((pA >> 34) & 0x3FFFu) * (1.0f / 31.0f);
        float s0s = (float)(unsigned)(pB & 0x1FFFFFu) * (1.0f / 256.0f) - 16.0f * cnt;
        float s1s = (float)(unsigned)((pB >> 21) & 0x1FFFFFu) * (1.0f / 256.0f) - 16.0f * cnt;
        float s2s = (float)(unsigned)((pB >> 42) & 0x1FFFFFu) * (1.0f / 256.0f) - 16.0f * cnt;
        float r0s = (float)(unsigned)(pC & 0x1FFFFFu) * (1.0f / 32.0f);
        float r1s = (float)(unsigned)((pC >> 21) & 0x1FFFFFu) * (1.0f / 32.0f);
        float r2s = (float)(unsigned)((pC >> 42) & 0x1FFFFFu) * (1.0f / 32.0f);
        float* d = sm + lane * 10;
        atomicAdd(d + 0, cnt);
        atomicAdd(d + 1, s0s);
        atomicAdd(d + 2, s1s);
        atomicAdd(d + 3, s2s);
        atomicAdd(d + 4, r0s);
        atomicAdd(d + 5, r1s);
        atomicAdd(d + 6, r2s);
        atomicAdd(d + 7, xs);
        atomicAdd(d + 8, ys);
        atomicAdd(d + 9, zs);
    }
    __syncthreads();
    if (tid < NSG * 10) {
        int id = tid / 10, f = tid % 10;
        float vsm = sm[tid];
        if (vsm != 0.0f) {
            int bi = b * NSG + id;
            float* dst;
            if (f == 0)      dst = &g_acc[OFF_CNT  + bi];
            else if (f < 4)  dst = &g_acc[OFF_SSUM + bi * 3 + (f - 1)];
            else if (f < 7)  dst = &g_acc[OFF_SSQ  + bi * 3 + (f - 4)];
            else             dst = &g_acc[OFF_XYZ  + bi * 3 + (f - 7)];
            atomicAdd(dst, vsm);
        }
    }
}

// ---------------------------------------------------------------- params (+ zero stats accumulators)
__global__ void k_params() {
    int t = threadIdx.x;
    if (t >= BB * NSG) return;
    int b = t / NSG, id = t % NSG;
    float cnt = g_acc[OFF_CNT + t];
    float safe = fmaxf(cnt, 1.0f);
    float varsum = 0.0f;
    float m[3];
    float xyz[3], cxyz[3];
#pragma unroll
    for (int c = 0; c < 3; c++) {
        float ss = g_acc[OFF_SSUM + t * 3 + c];
        float sq = g_acc[OFF_SSQ + t * 3 + c];
        float mm = ss / safe;
        m[c] = mm;
        varsum += (sq - 2.0f * mm * ss + cnt * mm * mm) / safe;
        xyz[c] = g_acc[OFF_XYZ + t * 3 + c];
        cxyz[c] = g_acc[OFF_CXYZ + t * 3 + c];
    }
    float ccnt = g_acc[OFF_CCNT + t];
    // zero for next graph replay
    g_acc[OFF_CNT + t] = 0.0f;
    g_acc[OFF_CCNT + t] = 0.0f;
#pragma unroll
    for (int c = 0; c < 3; c++) {
        g_acc[OFF_SSUM + t * 3 + c] = 0.0f;
        g_acc[OFF_SSQ + t * 3 + c] = 0.0f;
        g_acc[OFF_XYZ + t * 3 + c] = 0.0f;
        g_acc[OFF_CXYZ + t * 3 + c] = 0.0f;
    }
    if (id >= 1) {
        atomicAdd(&g_acc[OFF_VAR + b], varsum * (1.0f / (3.0f * NI)));
        bool one = (ccnt == 1.0f);
        int p = (b * NI + (id - 1)) * 3;
#pragma unroll
        for (int c = 0; c < 3; c++) {
            float cen = one ? cxyz[c] : xyz[c] / safe;
            g_acc[OFF_CEN + p + c] = cen;
            g_acc[OFF_S + p + c] = expf(10.0f * m[c]);
        }
    }
}

// ---------------------------------------------------------------- dist + SMEM histogram + seed loss
// grid (DGRID, BB, 4), 256 thr. Each block: 64 grid-stride iters, private
// 4-inst x 2048-bin smem bg histogram (32KB), single flush at the end.
// fg increments (1/17 of pairs) go straight to global RED.
__global__ void __launch_bounds__(256) k_dist(const float* __restrict__ pred,
                                              const int* __restrict__ inst,
                                              const int* __restrict__ lab) {
    __shared__ unsigned shist[4 * NBINS];     // 32KB
    __shared__ float r1[256], r2[256];
    int b = blockIdx.y;
    int quart = blockIdx.z;          // instances [quart*4, quart*4+4)
    int nbase = quart * 4;

    float c0[4], c1[4], c2[4], s0[4], s1[4], s2[4];
#pragma unroll
    for (int j = 0; j < 4; j++) {
        int p = (b * NI + nbase + j) * 3;
        s0[j] = g_acc[OFF_S + p];
        s1[j] = g_acc[OFF_S + p + 1];
        s2[j] = g_acc[OFF_S + p + 2];
        c0[j] = g_acc[OFF_CEN + p];
        c1[j] = g_acc[OFF_CEN + p + 1];
        c2[j] = g_acc[OFF_CEN + p + 2];
    }

    for (int i = threadIdx.x; i < 4 * NBINS; i += 256) shist[i] = 0u;
    __syncthreads();

    const float* pb = pred + (size_t)b * NCH * VV;
    const int* ib = inst + (size_t)b * VV;
    const int* lb = lab + (size_t)b * VV;
    unsigned* hfg = g_hfg + (size_t)b * NI * NBINS;

    float accbg = 0.0f, accfg = 0.0f;

    for (int v = blockIdx.x * 256 + threadIdx.x; v < VV; v += DGRID * 256) {
        float x = (float)(v & 255) * (1.0f / 1023.0f);
        float y = (float)((v >> 8) & 255) * (1.0f / 1023.0f);
        float z = (float)(v >> 16) * (1.0f / 31.0f);
        float e0 = fast_tanh(pb[v]) + x;
        float e1 = fast_tanh(pb[VV + v]) + y;
        float e2 = fast_tanh(pb[2 * VV + v]) + z;
        int id = ib[v];
        float down = 0.0f;
#pragma unroll
        for (int j = 0; j < 4; j++) {
            int n = nbase + j;
            float dx = e0 - c0[j], dy = e1 - c1[j], dz = e2 - c2[j];
            float arg = s0[j] * dx * dx + s1[j] * dy * dy + s2[j] * dz * dz;
            float d = __expf(-arg);
            bool fg = (id == n + 1);
            if (fg) down = d;
            float e = fg ? fmaf(-2.0f, d, 2.0f) : 2.0f * d;
            int bin = (int)(e * (NBINS * 0.5f));
            if (bin > NBINS - 1) bin = NBINS - 1;
            if (fg) atomicAdd(&hfg[n * NBINS + bin], 1u);
            else    atomicAdd(&shist[j * NBINS + bin], 1u);
        }
        bool own = (id > nbase && id <= nbase + 4);
        bool bg = (quart == 0) && (lb[v] == 0);
        if (own | bg) {
            float sd = 1.0f / (1.0f + __expf(-pb[6 * VV + v]));
            if (own) {
                float t = sd - down;
                accfg += t * t;
            }
            if (bg) accbg += sd * sd;
        }
    }

    __syncthreads();
    // flush bg histogram: one pre-aggregated RED per nonzero bin
    unsigned* dstbg = g_hbg + (size_t)(b * NI + nbase) * NBINS;
    for (int i = threadIdx.x; i < 4 * NBINS; i += 256) {
        unsigned c = shist[i];
        if (c) atomicAdd(&dstbg[i], c);
    }

    int t = threadIdx.x;
    r1[t] = accbg;
    r2[t] = accfg;
    __syncthreads();
    for (int s = 128; s > 0; s >>= 1) {
        if (t < s) { r1[t] += r1[t + s]; r2[t] += r2[t + s]; }
        __syncthreads();
    }
    if (t == 0) {
        if (quart == 0) atomicAdd(&g_acc[OFF_SBG + b], r1[0]);
        atomicAdd(&g_acc[OFF_SFG + b], r2[0]);
    }
}

// ---------------------------------------------------------------- lovasz from histogram (+ self-wipe)
// one block per (b,n); 1024 threads; CH=2 bins/thread; shfl-based prefix scan
__global__ void __launch_bounds__(1024) k_lovasz() {
    int bn = blockIdx.x;       // b*16 + n
    int b = bn >> 4;
    unsigned* HF = g_hfg + (size_t)bn * NBINS;
    unsigned* HB = g_hbg + (size_t)bn * NBINS;
    const int CH = NBINS / 1024;  // 2
    int t = threadIdx.x;
    int lane = t & 31, warp = t >> 5;

    // load my bins (descending error order: rank r = t*CH+i, bin = NBINS-1-r)
    float fA[CH], bA[CH];
    float locF = 0.0f, locB = 0.0f;
#pragma unroll
    for (int i = 0; i < CH; i++) {
        int bin = NBINS - 1 - (t * CH + i);
        fA[i] = (float)HF[bin];
        bA[i] = (float)HB[bin];
        locF += fA[i];
        locB += bA[i];
        HF[bin] = 0u;     // self-wipe for next replay
        HB[bin] = 0u;
    }

    // warp-level inclusive scan of (locF, locB) in thread order
    float incF = locF, incB = locB;
#pragma unroll
    for (int d = 1; d < 32; d <<= 1) {
        float vF = __shfl_up_sync(0xffffffffu, incF, d);
        float vB = __shfl_up_sync(0xffffffffu, incB, d);
        if (lane >= d) { incF += vF; incB += vB; }
    }
    __shared__ float wF[32], wB[32];
    __shared__ float sred[1024];
    __shared__ int sMinR;
    if (t == 0) sMinR = NBINS;
    if (lane == 31) { wF[warp] = incF; wB[warp] = incB; }
    __syncthreads();
    float offF = 0.0f, offB = 0.0f, G = 0.0f;
#pragma unroll
    for (int w = 0; w < 32; w++) {
        float f = wF[w];
        if (w < warp) { offF += f; offB += wB[w]; }
        G += f;
    }
    float P = offF + incF - locF;   // exclusive prefix (fg)
    float Q = offB + incB - locB;   // exclusive prefix (bg)

    float contrib = 0.0f;
    if (G > 0.0f) {
#pragma unroll
        for (int i = 0; i < CH; i++) {
            float f = fA[i], bb = bA[i];
            if (f > 0.0f || bb > 0.0f) {
                int bin = NBINS - 1 - (t * CH + i);
                float e = ((float)bin + 0.5f) * (2.0f / NBINS);
                float gq = G + Q;
                float num = (G - P) * bb + f * gq;   // cancellation-free jacc delta
                float den = gq * (gq + bb);
                contrib += e * num / den;
                P += f;
                Q += bb;
            }
        }
    } else {  // degenerate: no fg voxels -> loss = max error present
#pragma unroll
        for (int i = 0; i < CH; i++) {
            if (fA[i] > 0.0f || bA[i] > 0.0f) {
                atomicMin(&sMinR, t * CH + i);
                break;
            }
        }
    }
    sred[t] = contrib;
    __syncthreads();
    for (int s2 = 512; s2 > 0; s2 >>= 1) {
        if (t < s2) sred[t] += sred[t + s2];
        __syncthreads();
    }
    if (t == 0) {
        float total = sred[0];
        if (G <= 0.0f && sMinR < NBINS)
            total = ((float)(NBINS - 1 - sMinR) + 0.5f) * (2.0f / NBINS);
        atomicAdd(&g_acc[OFF_ILOSS + b], total);
    }
}

// ---------------------------------------------------------------- final combine (+ zero loss accumulators)
__global__ void k_final(float* out) {
    if (threadIdx.x == 0 && blockIdx.x == 0) {
        float r = 0.0f;
        for (int b = 0; b < BB; b++) {
            float il = g_acc[OFF_ILOSS + b] * (1.0f / NI);        // instance loss (W=1)
            float vl = g_acc[OFF_VAR + b];                        // var loss
            float sl = (g_acc[OFF_SBG + b] + 10.0f * g_acc[OFF_SFG + b]) * (1.0f / VV);
            r += il + 10.0f * vl + sl;
            g_acc[OFF_ILOSS + b] = 0.0f;
            g_acc[OFF_VAR + b] = 0.0f;
            g_acc[OFF_SBG + b] = 0.0f;
            g_acc[OFF_SFG + b] = 0.0f;
        }
        out[0] = r * (1.0f / BB);
    }
}

// ---------------------------------------------------------------- launch
extern "C" void kernel_launch(void* const* d_in, const int* in_sizes, int n_in,
                              void* d_out, int out_size) {
    const float* pred = (const float*)d_in[0];
    const int* inst = (const int*)d_in[1];
    const int* lab = (const int*)d_in[2];
    const int* cent = (const int*)d_in[3];

    {
        dim3 g(1024, BB);
        k_stats<<<g, 256>>>(pred, inst, cent);
    }
    k_params<<<1, 64>>>();
    {
        dim3 g(DGRID, BB, 4);
        k_dist<<<g, 256>>>(pred, inst, lab);
    }
    k_lovasz<<<BB * NI, 1024>>>();
    k_final<<<1, 1>>>((float*)d_out);
}